// round 1
// baseline (speedup 1.0000x reference)
#include <cuda_runtime.h>
#include <cstdint>

// ---------------------------------------------------------------------------
// GRU cell, B=16384, I=H=1024.
//   rh = hidden@W_r_h^T + b_r_h            (reused by r AND z gates - ref bug)
//   r  = sigmoid(input@W_r_i^T + b_r_i + rh)
//   z  = sigmoid(input@W_z_i^T + b_z_i + rh)
//   n  = tanh(input@W_n_i^T + b_n_i + r*(hidden@W_n_h^T + b_n_h))
//   out = (1-z)*n + z*hidden     (returned twice)
//
// Strategy: 5 GEMMs (M=16384,N=1024,K=1024) via mma.sync tf32 (rna rounding),
// results staged in __device__ scratch, then one fused elementwise kernel.
// ---------------------------------------------------------------------------

constexpr int Kdim = 1024;
constexpr int Ndim = 1024;
constexpr int MAX_B = 16384;
constexpr int BM = 128, BN = 128, BK = 32;
constexpr int LDSS = 36;                 // padded smem row stride (floats)
constexpr int STAGE = 128 * LDSS;        // words per operand per stage

__device__ float g_scr[5][(size_t)MAX_B * Ndim];  // ri, rh, zi, ni, nh

struct Params {
    const float* A[5];
    const float* W[5];
    const float* bias[5];
};

__device__ __forceinline__ uint32_t f2tf(float x) {
    uint32_t r;
    asm("cvt.rna.tf32.f32 %0, %1;" : "=r"(r) : "f"(x));
    return r;
}

__device__ __forceinline__ void mma_tf32(float c[4], const uint32_t a[4], const uint32_t b[2]) {
    asm volatile(
        "mma.sync.aligned.m16n8k8.row.col.f32.tf32.tf32.f32 "
        "{%0,%1,%2,%3}, {%4,%5,%6,%7}, {%8,%9}, {%0,%1,%2,%3};\n"
        : "+f"(c[0]), "+f"(c[1]), "+f"(c[2]), "+f"(c[3])
        : "r"(a[0]), "r"(a[1]), "r"(a[2]), "r"(a[3]),
          "r"(b[0]), "r"(b[1]));
}

__global__ void __launch_bounds__(256) gemm_tf32_kernel(Params p) {
    extern __shared__ uint32_t sm[];
    const int g = blockIdx.z;
    const float* __restrict__ A    = p.A[g];
    const float* __restrict__ W    = p.W[g];
    const float* __restrict__ bias = p.bias[g];
    float* __restrict__ C = g_scr[g];

    const int tid  = threadIdx.x;
    const int lane = tid & 31;
    const int warp = tid >> 5;
    const int wm = (warp & 1) * 64;      // 2 warps along M
    const int wn = (warp >> 1) * 32;     // 4 warps along N
    const int m0 = blockIdx.y * BM;
    const int n0 = blockIdx.x * BN;

    uint32_t* As = sm;                   // [2][STAGE]
    uint32_t* Bs = sm + 2 * STAGE;       // [2][STAGE]

    // staging map: 4 float4 per thread per operand
    int srow[4], sc4[4];
#pragma unroll
    for (int i = 0; i < 4; i++) {
        int f = i * 256 + tid;           // 1024 float4 = 128 rows x 8
        srow[i] = f >> 3;
        sc4[i]  = f & 7;
    }

    float4 ra[4], rb[4];
    // prologue: tile 0
#pragma unroll
    for (int i = 0; i < 4; i++) {
        ra[i] = *reinterpret_cast<const float4*>(&A[(size_t)(m0 + srow[i]) * Kdim + sc4[i] * 4]);
        rb[i] = *reinterpret_cast<const float4*>(&W[(size_t)(n0 + srow[i]) * Kdim + sc4[i] * 4]);
    }
#pragma unroll
    for (int i = 0; i < 4; i++) {
        uint32_t* pa = &As[srow[i] * LDSS + sc4[i] * 4];
        pa[0] = f2tf(ra[i].x); pa[1] = f2tf(ra[i].y);
        pa[2] = f2tf(ra[i].z); pa[3] = f2tf(ra[i].w);
        uint32_t* pb = &Bs[srow[i] * LDSS + sc4[i] * 4];
        pb[0] = f2tf(rb[i].x); pb[1] = f2tf(rb[i].y);
        pb[2] = f2tf(rb[i].z); pb[3] = f2tf(rb[i].w);
    }
    __syncthreads();

    float c[4][4][4];
#pragma unroll
    for (int mt = 0; mt < 4; mt++)
#pragma unroll
        for (int nt = 0; nt < 4; nt++)
#pragma unroll
            for (int q = 0; q < 4; q++) c[mt][nt][q] = 0.0f;

    const int NT = Kdim / BK;            // 32
    for (int kt = 0; kt < NT; kt++) {
        const int buf = kt & 1;
        if (kt + 1 < NT) {
            const int koff = (kt + 1) * BK;
#pragma unroll
            for (int i = 0; i < 4; i++) {
                ra[i] = *reinterpret_cast<const float4*>(&A[(size_t)(m0 + srow[i]) * Kdim + koff + sc4[i] * 4]);
                rb[i] = *reinterpret_cast<const float4*>(&W[(size_t)(n0 + srow[i]) * Kdim + koff + sc4[i] * 4]);
            }
        }
        // ---- compute on buf ----
        const uint32_t* Ab = &As[buf * STAGE];
        const uint32_t* Bb = &Bs[buf * STAGE];
#pragma unroll
        for (int kk = 0; kk < 4; kk++) {
            const int kb = kk * 8 + (lane & 3);
            uint32_t af[4][4];
            uint32_t bf[4][2];
#pragma unroll
            for (int mt = 0; mt < 4; mt++) {
                const int r = wm + mt * 16 + (lane >> 2);
                af[mt][0] = Ab[r * LDSS + kb];
                af[mt][1] = Ab[(r + 8) * LDSS + kb];
                af[mt][2] = Ab[r * LDSS + kb + 4];
                af[mt][3] = Ab[(r + 8) * LDSS + kb + 4];
            }
#pragma unroll
            for (int nt = 0; nt < 4; nt++) {
                const int rn = wn + nt * 8 + (lane >> 2);
                bf[nt][0] = Bb[rn * LDSS + kb];
                bf[nt][1] = Bb[rn * LDSS + kb + 4];
            }
#pragma unroll
            for (int mt = 0; mt < 4; mt++)
#pragma unroll
                for (int nt = 0; nt < 4; nt++)
                    mma_tf32(c[mt][nt], af[mt], bf[nt]);
        }
        if (kt + 1 < NT) {
            const int nb = buf ^ 1;
#pragma unroll
            for (int i = 0; i < 4; i++) {
                uint32_t* pa = &As[nb * STAGE + srow[i] * LDSS + sc4[i] * 4];
                pa[0] = f2tf(ra[i].x); pa[1] = f2tf(ra[i].y);
                pa[2] = f2tf(ra[i].z); pa[3] = f2tf(ra[i].w);
                uint32_t* pb = &Bs[nb * STAGE + srow[i] * LDSS + sc4[i] * 4];
                pb[0] = f2tf(rb[i].x); pb[1] = f2tf(rb[i].y);
                pb[2] = f2tf(rb[i].z); pb[3] = f2tf(rb[i].w);
            }
        }
        __syncthreads();
    }

    // ---- epilogue: +bias, store fp32 to scratch ----
#pragma unroll
    for (int nt = 0; nt < 4; nt++) {
        const int col = n0 + wn + nt * 8 + 2 * (lane & 3);
        const float bv0 = bias[col];
        const float bv1 = bias[col + 1];
#pragma unroll
        for (int mt = 0; mt < 4; mt++) {
            const int r0 = m0 + wm + mt * 16 + (lane >> 2);
            float2 v0 = make_float2(c[mt][nt][0] + bv0, c[mt][nt][1] + bv1);
            float2 v1 = make_float2(c[mt][nt][2] + bv0, c[mt][nt][3] + bv1);
            *reinterpret_cast<float2*>(&C[(size_t)r0 * Ndim + col]) = v0;
            *reinterpret_cast<float2*>(&C[(size_t)(r0 + 8) * Ndim + col]) = v1;
        }
    }
}

__device__ __forceinline__ float sigmoidf_(float x) {
    return 1.0f / (1.0f + __expf(-x));
}

__global__ void __launch_bounds__(256) gru_elem_kernel(
    const float* __restrict__ hidden, float* __restrict__ out,
    size_t n4, int dup) {
    size_t i = (size_t)blockIdx.x * 256 + threadIdx.x;
    if (i >= n4) return;
    const float4 ri = reinterpret_cast<const float4*>(g_scr[0])[i];
    const float4 rh = reinterpret_cast<const float4*>(g_scr[1])[i];
    const float4 zi = reinterpret_cast<const float4*>(g_scr[2])[i];
    const float4 ni = reinterpret_cast<const float4*>(g_scr[3])[i];
    const float4 nh = reinterpret_cast<const float4*>(g_scr[4])[i];
    const float4 h  = reinterpret_cast<const float4*>(hidden)[i];

    float4 o;
    {
        float r = sigmoidf_(ri.x + rh.x);
        float z = sigmoidf_(zi.x + rh.x);
        float n = tanhf(ni.x + r * nh.x);
        o.x = (1.0f - z) * n + z * h.x;
    }
    {
        float r = sigmoidf_(ri.y + rh.y);
        float z = sigmoidf_(zi.y + rh.y);
        float n = tanhf(ni.y + r * nh.y);
        o.y = (1.0f - z) * n + z * h.y;
    }
    {
        float r = sigmoidf_(ri.z + rh.z);
        float z = sigmoidf_(zi.z + rh.z);
        float n = tanhf(ni.z + r * nh.z);
        o.z = (1.0f - z) * n + z * h.z;
    }
    {
        float r = sigmoidf_(ri.w + rh.w);
        float z = sigmoidf_(zi.w + rh.w);
        float n = tanhf(ni.w + r * nh.w);
        o.w = (1.0f - z) * n + z * h.w;
    }
    reinterpret_cast<float4*>(out)[i] = o;
    if (dup) reinterpret_cast<float4*>(out)[i + n4] = o;
}

extern "C" void kernel_launch(void* const* d_in, const int* in_sizes, int n_in,
                              void* d_out, int out_size) {
    // metadata order: input, hidden, then (W,b) for r_i, r_h, z_i, z_h, n_i, n_h
    const float* input  = (const float*)d_in[0];
    const float* hidden = (const float*)d_in[1];

    Params p;
    // g0: ri = input @ W_r_i^T + b_r_i
    p.A[0] = input;  p.W[0] = (const float*)d_in[2];  p.bias[0] = (const float*)d_in[3];
    // g1: rh = hidden @ W_r_h^T + b_r_h
    p.A[1] = hidden; p.W[1] = (const float*)d_in[4];  p.bias[1] = (const float*)d_in[5];
    // g2: zi = input @ W_z_i^T + b_z_i      (W_z_h / b_z_h are unused per reference)
    p.A[2] = input;  p.W[2] = (const float*)d_in[6];  p.bias[2] = (const float*)d_in[7];
    // g3: ni = input @ W_n_i^T + b_n_i
    p.A[3] = input;  p.W[3] = (const float*)d_in[10]; p.bias[3] = (const float*)d_in[11];
    // g4: nh = hidden @ W_n_h^T + b_n_h
    p.A[4] = hidden; p.W[4] = (const float*)d_in[12]; p.bias[4] = (const float*)d_in[13];

    const int Brows = in_sizes[0] / Kdim;          // 16384
    const size_t BHsz = (size_t)Brows * Ndim;

    const int smem_bytes = 4 * STAGE * 4;          // 73728 B
    cudaFuncSetAttribute(gemm_tf32_kernel,
                         cudaFuncAttributeMaxDynamicSharedMemorySize, smem_bytes);

    dim3 grid(Ndim / BN, Brows / BM, 5);
    gemm_tf32_kernel<<<grid, 256, smem_bytes>>>(p);

    const size_t n4 = BHsz / 4;
    const int dup = ((size_t)out_size >= 2 * BHsz) ? 1 : 0;
    gru_elem_kernel<<<(unsigned)((n4 + 255) / 256), 256>>>(hidden, (float*)d_out, n4, dup);
}

// round 16
// speedup vs baseline: 1.5529x; 1.5529x over previous
#include <cuda_runtime.h>
#include <cuda_fp16.h>
#include <cstdint>

// ---------------------------------------------------------------------------
// GRU cell, B=16384, I=H=1024.  Harness PTX target is sm_103 (no 'a'), so no
// tcgen05 — use fp16 mma.sync.m16n8k16 (same 10 mantissa bits as tf32, 2x rate).
//   prepass: fp32 -> fp16 (RN) for input/hidden/5 weights
//   gemm:    5 GEMMs [16384x1024]x[1024x1024]^T, +bias, fp16 scratch out
//   elem:    fused sigmoid/tanh/gate -> fp32 out (x2)
// ---------------------------------------------------------------------------

constexpr int Kdim = 1024;
constexpr int Ndim = 1024;
constexpr int Brows = 16384;
constexpr int BK = 32;                   // fp16 k per stage
constexpr int NSTEP = Kdim / BK;         // 32
constexpr int ST = 3;                    // pipeline stages
constexpr int ROWB = 80;                 // smem row stride bytes (32+8 fp16)
constexpr int TILEB = 128 * ROWB;        // 10240 B per operand tile
constexpr int STAGEB = 2 * TILEB;        // 20480 B per stage

__device__ __half g_inh [(size_t)Brows * Kdim];
__device__ __half g_hidh[(size_t)Brows * Kdim];
__device__ __half g_wh[5][(size_t)Ndim * Kdim];
__device__ __half g_scr[5][(size_t)Brows * Ndim];   // ri, rh, zi, ni, nh

__device__ __forceinline__ uint32_t smem_u32(const void* p) {
    uint32_t a;
    asm("{ .reg .u64 t; cvta.to.shared.u64 t, %1; cvt.u32.u64 %0, t; }" : "=r"(a) : "l"(p));
    return a;
}
#define CP_ASYNC16(dst, src) \
    asm volatile("cp.async.cg.shared.global [%0], [%1], 16;" :: "r"(dst), "l"(src))
#define CP_COMMIT() asm volatile("cp.async.commit_group;" ::: "memory")
#define CP_WAIT1()  asm volatile("cp.async.wait_group 1;" ::: "memory")
#define CP_WAIT0()  asm volatile("cp.async.wait_group 0;" ::: "memory")

__device__ __forceinline__ void ldsm_x4(uint32_t r[4], uint32_t addr) {
    asm volatile("ldmatrix.sync.aligned.m8n8.x4.shared.b16 {%0,%1,%2,%3}, [%4];"
                 : "=r"(r[0]), "=r"(r[1]), "=r"(r[2]), "=r"(r[3]) : "r"(addr));
}
__device__ __forceinline__ void mma_fp16(float c[4], const uint32_t a[4], const uint32_t b[2]) {
    asm volatile(
        "mma.sync.aligned.m16n8k16.row.col.f32.f16.f16.f32 "
        "{%0,%1,%2,%3}, {%4,%5,%6,%7}, {%8,%9}, {%0,%1,%2,%3};\n"
        : "+f"(c[0]), "+f"(c[1]), "+f"(c[2]), "+f"(c[3])
        : "r"(a[0]), "r"(a[1]), "r"(a[2]), "r"(a[3]), "r"(b[0]), "r"(b[1]));
}

// ---------------- prepass: fp32 -> fp16 (single fused grid) ----------------
// seg 0: input (16384 blocks), seg 1: hidden (16384), segs 2..6: weights (1024 each)
struct CvtP {
    const float4* src[7];
};
__global__ void __launch_bounds__(256) cvt_all(CvtP p) {
    const int seg = blockIdx.y;
    const size_t i = (size_t)blockIdx.x * 256 + threadIdx.x;
    // weight segments are smaller: guard
    if (seg >= 2 && blockIdx.x >= 1024) return;
    const float4 v = p.src[seg][i];
    __half2 h0 = __floats2half2_rn(v.x, v.y);
    __half2 h1 = __floats2half2_rn(v.z, v.w);
    uint2 o = make_uint2(*(uint32_t*)&h0, *(uint32_t*)&h1);
    uint2* dst;
    if (seg == 0)      dst = reinterpret_cast<uint2*>(g_inh);
    else if (seg == 1) dst = reinterpret_cast<uint2*>(g_hidh);
    else               dst = reinterpret_cast<uint2*>(g_wh[seg - 2]);
    dst[i] = o;
}

// ---------------- fp16 GEMM ----------------
struct GemmP {
    const __half* A[5];
    const __half* W[5];
    const float*  bias[5];
};

__global__ void __launch_bounds__(256, 2) gemm_fp16(GemmP p) {
    extern __shared__ char smem[];
    const uint32_t sb = smem_u32(smem);
    const int g = blockIdx.z;
    const __half* __restrict__ A = p.A[g];
    const __half* __restrict__ W = p.W[g];
    const float* __restrict__ bias = p.bias[g];
    __half* __restrict__ C = g_scr[g];

    const int tid = threadIdx.x;
    const int lane = tid & 31;
    const int warp = tid >> 5;
    const int wm = (warp & 1) * 64;          // 2 warps along M, tile 64
    const int wn = (warp >> 1) * 32;         // 4 warps along N, tile 32
    const int m0 = blockIdx.y * 128;
    const int n0 = blockIdx.x * 128;

    // staging map: 512 16B-chunks per operand; 2 chunks/thread/operand
    auto issue_stage = [&](int t) {
        const uint32_t sbase = sb + (uint32_t)(t % ST) * STAGEB;
        const int k0 = t * BK;
#pragma unroll
        for (int i = 0; i < 2; i++) {
            const int u = tid + i * 256;
            const int r = u >> 2, c4 = u & 3;
            CP_ASYNC16(sbase + r * ROWB + c4 * 16,
                       A + (size_t)(m0 + r) * Kdim + k0 + c4 * 8);
        }
#pragma unroll
        for (int i = 0; i < 2; i++) {
            const int u = tid + i * 256;
            const int r = u >> 2, c4 = u & 3;
            CP_ASYNC16(sbase + TILEB + r * ROWB + c4 * 16,
                       W + (size_t)(n0 + r) * Kdim + k0 + c4 * 8);
        }
        CP_COMMIT();
    };

    issue_stage(0);
    issue_stage(1);

    float c[4][4][4];
#pragma unroll
    for (int mt = 0; mt < 4; mt++)
#pragma unroll
        for (int nt = 0; nt < 4; nt++)
#pragma unroll
            for (int q = 0; q < 4; q++) c[mt][nt][q] = 0.0f;

    // ldmatrix lane address components (A tile)
    const int lrow = lane & 15;              // row within 16
    const int lkof = (lane >> 4) * 16;       // 8 fp16 = 16 bytes
    // B load components
    const int brow = lane >> 2;              // n within 8
    const int bkof = (lane & 3) * 4;         // 2 fp16 = 4 bytes

    for (int s = 0; s < NSTEP; s++) {
        CP_WAIT1();
        __syncthreads();
        if (s + 2 < NSTEP) issue_stage(s + 2);

        const uint32_t sbase = sb + (uint32_t)(s % ST) * STAGEB;
        const uint32_t abase = sbase;
        const uint32_t bbase = sbase + TILEB;

#pragma unroll
        for (int kk = 0; kk < 2; kk++) {     // two k16 slices
            uint32_t af[4][4];
#pragma unroll
            for (int mt = 0; mt < 4; mt++) {
                const uint32_t addr =
                    abase + (uint32_t)(wm + mt * 16 + lrow) * ROWB + kk * 32 + lkof;
                ldsm_x4(af[mt], addr);
            }
            uint32_t bf[4][2];
#pragma unroll
            for (int nt = 0; nt < 4; nt++) {
                const uint32_t ra =
                    bbase + (uint32_t)(wn + nt * 8 + brow) * ROWB + kk * 32 + bkof;
                asm volatile("ld.shared.b32 %0, [%1];" : "=r"(bf[nt][0]) : "r"(ra));
                asm volatile("ld.shared.b32 %0, [%1];" : "=r"(bf[nt][1]) : "r"(ra + 16));
            }
#pragma unroll
            for (int mt = 0; mt < 4; mt++)
#pragma unroll
                for (int nt = 0; nt < 4; nt++)
                    mma_fp16(c[mt][nt], af[mt], bf[nt]);
        }
        __syncthreads();
    }
    CP_WAIT0();

    // epilogue: +bias (fp32), store fp16 scratch
#pragma unroll
    for (int nt = 0; nt < 4; nt++) {
        const int col = n0 + wn + nt * 8 + 2 * (lane & 3);
        const float bv0 = bias[col];
        const float bv1 = bias[col + 1];
#pragma unroll
        for (int mt = 0; mt < 4; mt++) {
            const int r0 = m0 + wm + mt * 16 + (lane >> 2);
            __half2 v0 = __floats2half2_rn(c[mt][nt][0] + bv0, c[mt][nt][1] + bv1);
            __half2 v1 = __floats2half2_rn(c[mt][nt][2] + bv0, c[mt][nt][3] + bv1);
            *reinterpret_cast<__half2*>(&C[(size_t)r0 * Ndim + col]) = v0;
            *reinterpret_cast<__half2*>(&C[(size_t)(r0 + 8) * Ndim + col]) = v1;
        }
    }
}

// ---------------- fused elementwise ----------------
__device__ __forceinline__ float sigmoidf_(float x) { return 1.0f / (1.0f + __expf(-x)); }

__global__ void __launch_bounds__(256) gru_elem_kernel(
    const float* __restrict__ hidden, float* __restrict__ out,
    size_t n4, int dup) {
    const size_t i = (size_t)blockIdx.x * 256 + threadIdx.x;
    if (i >= n4) return;
    const uint2 ri4 = reinterpret_cast<const uint2*>(g_scr[0])[i];
    const uint2 rh4 = reinterpret_cast<const uint2*>(g_scr[1])[i];
    const uint2 zi4 = reinterpret_cast<const uint2*>(g_scr[2])[i];
    const uint2 ni4 = reinterpret_cast<const uint2*>(g_scr[3])[i];
    const uint2 nh4 = reinterpret_cast<const uint2*>(g_scr[4])[i];
    const float4 h = reinterpret_cast<const float4*>(hidden)[i];

    float ri[4], rh[4], zi[4], ni[4], nh[4];
    {
        float2 t;
        t = __half22float2(*(const __half2*)&ri4.x); ri[0] = t.x; ri[1] = t.y;
        t = __half22float2(*(const __half2*)&ri4.y); ri[2] = t.x; ri[3] = t.y;
        t = __half22float2(*(const __half2*)&rh4.x); rh[0] = t.x; rh[1] = t.y;
        t = __half22float2(*(const __half2*)&rh4.y); rh[2] = t.x; rh[3] = t.y;
        t = __half22float2(*(const __half2*)&zi4.x); zi[0] = t.x; zi[1] = t.y;
        t = __half22float2(*(const __half2*)&zi4.y); zi[2] = t.x; zi[3] = t.y;
        t = __half22float2(*(const __half2*)&ni4.x); ni[0] = t.x; ni[1] = t.y;
        t = __half22float2(*(const __half2*)&ni4.y); ni[2] = t.x; ni[3] = t.y;
        t = __half22float2(*(const __half2*)&nh4.x); nh[0] = t.x; nh[1] = t.y;
        t = __half22float2(*(const __half2*)&nh4.y); nh[2] = t.x; nh[3] = t.y;
    }
    const float hv[4] = {h.x, h.y, h.z, h.w};
    float o[4];
#pragma unroll
    for (int q = 0; q < 4; q++) {
        const float r = sigmoidf_(ri[q] + rh[q]);
        const float z = sigmoidf_(zi[q] + rh[q]);
        const float n = tanhf(ni[q] + r * nh[q]);
        o[q] = (1.0f - z) * n + z * hv[q];
    }
    float4 ov = make_float4(o[0], o[1], o[2], o[3]);
    reinterpret_cast<float4*>(out)[i] = ov;
    if (dup) reinterpret_cast<float4*>(out)[i + n4] = ov;
}

// ---------------- launch ----------------
extern "C" void kernel_launch(void* const* d_in, const int* in_sizes, int n_in,
                              void* d_out, int out_size) {
    const float* input  = (const float*)d_in[0];
    const float* hidden = (const float*)d_in[1];

    CvtP cp;
    cp.src[0] = (const float4*)input;
    cp.src[1] = (const float4*)hidden;
    cp.src[2] = (const float4*)d_in[2];    // W_r_i
    cp.src[3] = (const float4*)d_in[4];    // W_r_h
    cp.src[4] = (const float4*)d_in[6];    // W_z_i
    cp.src[5] = (const float4*)d_in[10];   // W_n_i
    cp.src[6] = (const float4*)d_in[12];   // W_n_h
    cvt_all<<<dim3(16384, 7), 256>>>(cp);

    __half* gin;  cudaGetSymbolAddress((void**)&gin, g_inh);
    __half* ghi;  cudaGetSymbolAddress((void**)&ghi, g_hidh);
    __half* gw0;  cudaGetSymbolAddress((void**)&gw0, g_wh);
    const size_t WSZ = (size_t)Ndim * Kdim;

    GemmP gp;
    // g0: ri = input @ W_r_i^T
    gp.A[0] = gin; gp.W[0] = gw0 + 0 * WSZ; gp.bias[0] = (const float*)d_in[3];
    // g1: rh = hidden @ W_r_h^T
    gp.A[1] = ghi; gp.W[1] = gw0 + 1 * WSZ; gp.bias[1] = (const float*)d_in[5];
    // g2: zi = input @ W_z_i^T   (W_z_h/b_z_h dead per reference bug)
    gp.A[2] = gin; gp.W[2] = gw0 + 2 * WSZ; gp.bias[2] = (const float*)d_in[7];
    // g3: ni = input @ W_n_i^T
    gp.A[3] = gin; gp.W[3] = gw0 + 3 * WSZ; gp.bias[3] = (const float*)d_in[11];
    // g4: nh = hidden @ W_n_h^T
    gp.A[4] = ghi; gp.W[4] = gw0 + 4 * WSZ; gp.bias[4] = (const float*)d_in[13];

    const int smem_bytes = ST * STAGEB;                 // 61440
    cudaFuncSetAttribute(gemm_fp16, cudaFuncAttributeMaxDynamicSharedMemorySize,
                         smem_bytes);
    gemm_fp16<<<dim3(8, 128, 5), 256, smem_bytes>>>(gp);

    const size_t n4 = (size_t)Brows * Ndim / 4;
    const int dup = ((size_t)out_size >= 2 * (size_t)Brows * Ndim) ? 1 : 0;
    gru_elem_kernel<<<(unsigned)((n4 + 255) / 256), 256>>>(hidden, (float*)d_out, n4, dup);
}

// round 17
// speedup vs baseline: 1.8235x; 1.1743x over previous
#include <cuda_runtime.h>
#include <cuda_fp16.h>
#include <cstdint>

// ---------------------------------------------------------------------------
// GRU cell, B=16384, I=H=1024.  fp16 mma.sync.m16n8k16 path (sm_103 target).
//   prepass: fp32 -> fp16 (RN), batched MLP=4 grid (fix: was latency-bound)
//   gemm:    5 GEMMs [16384x1024]x[1024x1024]^T, +bias, fp16 scratch out
//   elem:    fused sigmoid/tanh/gate -> fp32 out (x2)
// ---------------------------------------------------------------------------

constexpr int Kdim = 1024;
constexpr int Ndim = 1024;
constexpr int Brows = 16384;
constexpr int BK = 32;                   // fp16 k per stage
constexpr int NSTEP = Kdim / BK;         // 32
constexpr int ST = 3;                    // pipeline stages
constexpr int ROWB = 80;                 // smem row stride bytes (32+8 fp16)
constexpr int TILEB = 128 * ROWB;        // 10240 B per operand tile
constexpr int STAGEB = 2 * TILEB;        // 20480 B per stage

__device__ __half g_inh [(size_t)Brows * Kdim];
__device__ __half g_hidh[(size_t)Brows * Kdim];
__device__ __half g_wh[5][(size_t)Ndim * Kdim];
__device__ __half g_scr[5][(size_t)Brows * Ndim];   // ri, rh, zi, ni, nh

__device__ __forceinline__ uint32_t smem_u32(const void* p) {
    uint32_t a;
    asm("{ .reg .u64 t; cvta.to.shared.u64 t, %1; cvt.u32.u64 %0, t; }" : "=r"(a) : "l"(p));
    return a;
}
#define CP_ASYNC16(dst, src) \
    asm volatile("cp.async.cg.shared.global [%0], [%1], 16;" :: "r"(dst), "l"(src))
#define CP_COMMIT() asm volatile("cp.async.commit_group;" ::: "memory")
#define CP_WAIT1()  asm volatile("cp.async.wait_group 1;" ::: "memory")
#define CP_WAIT0()  asm volatile("cp.async.wait_group 0;" ::: "memory")

__device__ __forceinline__ void ldsm_x4(uint32_t r[4], uint32_t addr) {
    asm volatile("ldmatrix.sync.aligned.m8n8.x4.shared.b16 {%0,%1,%2,%3}, [%4];"
                 : "=r"(r[0]), "=r"(r[1]), "=r"(r[2]), "=r"(r[3]) : "r"(addr));
}
__device__ __forceinline__ void mma_fp16(float c[4], const uint32_t a[4], const uint32_t b[2]) {
    asm volatile(
        "mma.sync.aligned.m16n8k16.row.col.f32.f16.f16.f32 "
        "{%0,%1,%2,%3}, {%4,%5,%6,%7}, {%8,%9}, {%0,%1,%2,%3};\n"
        : "+f"(c[0]), "+f"(c[1]), "+f"(c[2]), "+f"(c[3])
        : "r"(a[0]), "r"(a[1]), "r"(a[2]), "r"(a[3]), "r"(b[0]), "r"(b[1]));
}

// ---------------- prepass: fp32 -> fp16, MLP=4 ----------------
// Grid dim3(4096, 7).  seg 0/1 (input/hidden): 4,194,304 float4 each;
// thread handles indices i + k*G (G = 4096*256), k = 0..3 — 4 independent
// loads batched for MLP.  segs 2..6 (weights): 262,144 float4; only blocks
// < 256 participate, stride 65536.
struct CvtP {
    const float4* src[7];
};
__global__ void __launch_bounds__(256) cvt_all(CvtP p) {
    const int seg = blockIdx.y;
    const unsigned i = blockIdx.x * 256u + threadIdx.x;
    const float4* __restrict__ src = p.src[seg];
    uint2* dst;
    unsigned stride;
    if (seg == 0)      { dst = reinterpret_cast<uint2*>(g_inh);  stride = 4096u * 256u; }
    else if (seg == 1) { dst = reinterpret_cast<uint2*>(g_hidh); stride = 4096u * 256u; }
    else {
        if (blockIdx.x >= 256) return;
        dst = reinterpret_cast<uint2*>(g_wh[seg - 2]);
        stride = 256u * 256u;
    }
    float4 v[4];
#pragma unroll
    for (int k = 0; k < 4; k++) v[k] = src[i + k * stride];      // batched: MLP=4
#pragma unroll
    for (int k = 0; k < 4; k++) {
        __half2 h0 = __floats2half2_rn(v[k].x, v[k].y);
        __half2 h1 = __floats2half2_rn(v[k].z, v[k].w);
        dst[i + k * stride] = make_uint2(*(uint32_t*)&h0, *(uint32_t*)&h1);
    }
}

// ---------------- fp16 GEMM (unchanged — hit predicted ~620us) ----------------
struct GemmP {
    const __half* A[5];
    const __half* W[5];
    const float*  bias[5];
};

__global__ void __launch_bounds__(256, 2) gemm_fp16(GemmP p) {
    extern __shared__ char smem[];
    const uint32_t sb = smem_u32(smem);
    const int g = blockIdx.z;
    const __half* __restrict__ A = p.A[g];
    const __half* __restrict__ W = p.W[g];
    const float* __restrict__ bias = p.bias[g];
    __half* __restrict__ C = g_scr[g];

    const int tid = threadIdx.x;
    const int lane = tid & 31;
    const int warp = tid >> 5;
    const int wm = (warp & 1) * 64;          // 2 warps along M, tile 64
    const int wn = (warp >> 1) * 32;         // 4 warps along N, tile 32
    const int m0 = blockIdx.y * 128;
    const int n0 = blockIdx.x * 128;

    auto issue_stage = [&](int t) {
        const uint32_t sbase = sb + (uint32_t)(t % ST) * STAGEB;
        const int k0 = t * BK;
#pragma unroll
        for (int i = 0; i < 2; i++) {
            const int u = tid + i * 256;
            const int r = u >> 2, c4 = u & 3;
            CP_ASYNC16(sbase + r * ROWB + c4 * 16,
                       A + (size_t)(m0 + r) * Kdim + k0 + c4 * 8);
        }
#pragma unroll
        for (int i = 0; i < 2; i++) {
            const int u = tid + i * 256;
            const int r = u >> 2, c4 = u & 3;
            CP_ASYNC16(sbase + TILEB + r * ROWB + c4 * 16,
                       W + (size_t)(n0 + r) * Kdim + k0 + c4 * 8);
        }
        CP_COMMIT();
    };

    issue_stage(0);
    issue_stage(1);

    float c[4][4][4];
#pragma unroll
    for (int mt = 0; mt < 4; mt++)
#pragma unroll
        for (int nt = 0; nt < 4; nt++)
#pragma unroll
            for (int q = 0; q < 4; q++) c[mt][nt][q] = 0.0f;

    const int lrow = lane & 15;              // row within 16
    const int lkof = (lane >> 4) * 16;       // 8 fp16 = 16 bytes
    const int brow = lane >> 2;              // n within 8
    const int bkof = (lane & 3) * 4;         // 2 fp16 = 4 bytes

    for (int s = 0; s < NSTEP; s++) {
        CP_WAIT1();
        __syncthreads();
        if (s + 2 < NSTEP) issue_stage(s + 2);

        const uint32_t sbase = sb + (uint32_t)(s % ST) * STAGEB;
        const uint32_t abase = sbase;
        const uint32_t bbase = sbase + TILEB;

#pragma unroll
        for (int kk = 0; kk < 2; kk++) {     // two k16 slices
            uint32_t af[4][4];
#pragma unroll
            for (int mt = 0; mt < 4; mt++) {
                const uint32_t addr =
                    abase + (uint32_t)(wm + mt * 16 + lrow) * ROWB + kk * 32 + lkof;
                ldsm_x4(af[mt], addr);
            }
            uint32_t bf[4][2];
#pragma unroll
            for (int nt = 0; nt < 4; nt++) {
                const uint32_t ra =
                    bbase + (uint32_t)(wn + nt * 8 + brow) * ROWB + kk * 32 + bkof;
                asm volatile("ld.shared.b32 %0, [%1];" : "=r"(bf[nt][0]) : "r"(ra));
                asm volatile("ld.shared.b32 %0, [%1];" : "=r"(bf[nt][1]) : "r"(ra + 16));
            }
#pragma unroll
            for (int mt = 0; mt < 4; mt++)
#pragma unroll
                for (int nt = 0; nt < 4; nt++)
                    mma_fp16(c[mt][nt], af[mt], bf[nt]);
        }
        __syncthreads();
    }
    CP_WAIT0();

    // epilogue: +bias (fp32), store fp16 scratch
#pragma unroll
    for (int nt = 0; nt < 4; nt++) {
        const int col = n0 + wn + nt * 8 + 2 * (lane & 3);
        const float bv0 = bias[col];
        const float bv1 = bias[col + 1];
#pragma unroll
        for (int mt = 0; mt < 4; mt++) {
            const int r0 = m0 + wm + mt * 16 + (lane >> 2);
            __half2 v0 = __floats2half2_rn(c[mt][nt][0] + bv0, c[mt][nt][1] + bv1);
            __half2 v1 = __floats2half2_rn(c[mt][nt][2] + bv0, c[mt][nt][3] + bv1);
            *reinterpret_cast<__half2*>(&C[(size_t)r0 * Ndim + col]) = v0;
            *reinterpret_cast<__half2*>(&C[(size_t)(r0 + 8) * Ndim + col]) = v1;
        }
    }
}

// ---------------- fused elementwise ----------------
__device__ __forceinline__ float sigmoidf_(float x) { return 1.0f / (1.0f + __expf(-x)); }

__global__ void __launch_bounds__(256) gru_elem_kernel(
    const float* __restrict__ hidden, float* __restrict__ out,
    size_t n4, int dup) {
    const size_t i = (size_t)blockIdx.x * 256 + threadIdx.x;
    if (i >= n4) return;
    const uint2 ri4 = reinterpret_cast<const uint2*>(g_scr[0])[i];
    const uint2 rh4 = reinterpret_cast<const uint2*>(g_scr[1])[i];
    const uint2 zi4 = reinterpret_cast<const uint2*>(g_scr[2])[i];
    const uint2 ni4 = reinterpret_cast<const uint2*>(g_scr[3])[i];
    const uint2 nh4 = reinterpret_cast<const uint2*>(g_scr[4])[i];
    const float4 h = reinterpret_cast<const float4*>(hidden)[i];

    float ri[4], rh[4], zi[4], ni[4], nh[4];
    {
        float2 t;
        t = __half22float2(*(const __half2*)&ri4.x); ri[0] = t.x; ri[1] = t.y;
        t = __half22float2(*(const __half2*)&ri4.y); ri[2] = t.x; ri[3] = t.y;
        t = __half22float2(*(const __half2*)&rh4.x); rh[0] = t.x; rh[1] = t.y;
        t = __half22float2(*(const __half2*)&rh4.y); rh[2] = t.x; rh[3] = t.y;
        t = __half22float2(*(const __half2*)&zi4.x); zi[0] = t.x; zi[1] = t.y;
        t = __half22float2(*(const __half2*)&zi4.y); zi[2] = t.x; zi[3] = t.y;
        t = __half22float2(*(const __half2*)&ni4.x); ni[0] = t.x; ni[1] = t.y;
        t = __half22float2(*(const __half2*)&ni4.y); ni[2] = t.x; ni[3] = t.y;
        t = __half22float2(*(const __half2*)&nh4.x); nh[0] = t.x; nh[1] = t.y;
        t = __half22float2(*(const __half2*)&nh4.y); nh[2] = t.x; nh[3] = t.y;
    }
    const float hv[4] = {h.x, h.y, h.z, h.w};
    float o[4];
#pragma unroll
    for (int q = 0; q < 4; q++) {
        const float r = sigmoidf_(ri[q] + rh[q]);
        const float z = sigmoidf_(zi[q] + rh[q]);
        const float n = tanhf(ni[q] + r * nh[q]);
        o[q] = (1.0f - z) * n + z * hv[q];
    }
    float4 ov = make_float4(o[0], o[1], o[2], o[3]);
    reinterpret_cast<float4*>(out)[i] = ov;
    if (dup) reinterpret_cast<float4*>(out)[i + n4] = ov;
}

// ---------------- launch ----------------
extern "C" void kernel_launch(void* const* d_in, const int* in_sizes, int n_in,
                              void* d_out, int out_size) {
    const float* input  = (const float*)d_in[0];
    const float* hidden = (const float*)d_in[1];

    CvtP cp;
    cp.src[0] = (const float4*)input;
    cp.src[1] = (const float4*)hidden;
    cp.src[2] = (const float4*)d_in[2];    // W_r_i
    cp.src[3] = (const float4*)d_in[4];    // W_r_h
    cp.src[4] = (const float4*)d_in[6];    // W_z_i
    cp.src[5] = (const float4*)d_in[10];   // W_n_i
    cp.src[6] = (const float4*)d_in[12];   // W_n_h
    cvt_all<<<dim3(4096, 7), 256>>>(cp);

    __half* gin;  cudaGetSymbolAddress((void**)&gin, g_inh);
    __half* ghi;  cudaGetSymbolAddress((void**)&ghi, g_hidh);
    __half* gw0;  cudaGetSymbolAddress((void**)&gw0, g_wh);
    const size_t WSZ = (size_t)Ndim * Kdim;

    GemmP gp;
    // g0: ri = input @ W_r_i^T
    gp.A[0] = gin; gp.W[0] = gw0 + 0 * WSZ; gp.bias[0] = (const float*)d_in[3];
    // g1: rh = hidden @ W_r_h^T
    gp.A[1] = ghi; gp.W[1] = gw0 + 1 * WSZ; gp.bias[1] = (const float*)d_in[5];
    // g2: zi = input @ W_z_i^T   (W_z_h/b_z_h dead per reference bug)
    gp.A[2] = gin; gp.W[2] = gw0 + 2 * WSZ; gp.bias[2] = (const float*)d_in[7];
    // g3: ni = input @ W_n_i^T
    gp.A[3] = gin; gp.W[3] = gw0 + 3 * WSZ; gp.bias[3] = (const float*)d_in[11];
    // g4: nh = hidden @ W_n_h^T
    gp.A[4] = ghi; gp.W[4] = gw0 + 4 * WSZ; gp.bias[4] = (const float*)d_in[13];

    const int smem_bytes = ST * STAGEB;                 // 61440
    cudaFuncSetAttribute(gemm_fp16, cudaFuncAttributeMaxDynamicSharedMemorySize,
                         smem_bytes);
    gemm_fp16<<<dim3(8, 128, 5), 256, smem_bytes>>>(gp);

    const size_t n4 = (size_t)Brows * Ndim / 4;
    const int dup = ((size_t)out_size >= 2 * (size_t)Brows * Ndim) ? 1 : 0;
    gru_elem_kernel<<<(unsigned)((n4 + 255) / 256), 256>>>(hidden, (float*)d_out, n4, dup);
}